// round 10
// baseline (speedup 1.0000x reference)
#include <cuda_runtime.h>

#define MEMSZ 16384
#define OUTSZ 64
#define NCTX  (MEMSZ + 5 + OUTSZ)   // 16453
#define MAXST 16                    // num_steps capacity (spec: 16)

// ---------------- kernel 1: streaming row copy ----------------
__global__ void __launch_bounds__(256)
copy_kernel(const float4* __restrict__ src, float4* __restrict__ dst, size_t n4) {
    size_t base = (size_t)blockIdx.x * 4096 + threadIdx.x;  // 4096 float4 per row
    #pragma unroll
    for (int k = 0; k < 16; k++) {
        size_t i = base + (size_t)k * 256;
        if (i < n4) dst[i] = src[i];
    }
}

// ---------------- math helpers ----------------
__device__ __forceinline__ float sgm(float x) {        // fast sigmoid
    return __fdividef(1.0f, 1.0f + __expf(-x));
}
// eq_gate(diff) with a single shared exponential (see R6 derivation)
__device__ __forceinline__ float eq_gate(float diff) {
    const float C = 2.0611536e-9f;          // e^-20
    float u  = 20.0f * diff;
    float t  = __expf(-u);
    float it = __fdividef(1.0f, t);         // e^u
    float s_u  = __fdividef(1.0f, 1.0f + t);
    float s_nu = 1.0f - s_u;
    float s_up = __fdividef(1.0f, 1.0f + t * C);
    float s_um = __fdividef(1.0f, 1.0f + it * C);
    float st1 = ((u + 20.0f) * s_up - u * s_u) * 0.05f;
    float st2 = ((20.0f - u) * s_um + u * s_nu) * 0.05f;
    return st1 * st2;
}
__device__ __forceinline__ int clampi_(float a) {
    return (int)fminf(fmaxf(a, 0.0f), (float)(NCTX - 1));
}

// ---------------- kernel 2: speculative state machine ----------------
__global__ void __launch_bounds__(32)
machine_kernel(const float* __restrict__ mem,
               const float* __restrict__ outp,
               const float* __restrict__ ax_in,
               const int* __restrict__ pc_in,
               const int* __restrict__ sp_in,
               const int* __restrict__ bp_in,
               const int* __restrict__ ol_in,
               const int* __restrict__ ns_ptr,
               float* __restrict__ dst,
               int B) {
    const int r = blockIdx.x * 32 + threadIdx.x;
    if (r >= B) return;

    const float* mrow = mem + (size_t)r * MEMSZ;
    const float* orow = outp + (size_t)r * OUTSZ;
    float* drow = dst + (size_t)r * MEMSZ;

    int ns = ns_ptr ? ns_ptr[0] : MAXST;
    if (ns > MAXST) ns = MAXST;

    float pc = (float)pc_in[r];
    float sp = (float)sp_in[r];
    const float bp = (float)bp_in[r];
    float ax = ax_in[r];
    const float ol = (float)ol_in[r];

    // ---- phase 1: prefetch pc-path (pc_t = pc0 + 8t, deterministic) ----
    float pv[MAXST];
    #pragma unroll
    for (int t = 0; t < MAXST; t++) {
        int api = clampi_(pc + 8.0f * (float)t);
        int ad = (api < MEMSZ) ? api : (api - MEMSZ);
        pv[t] = __ldg(mrow + ad);
    }

    // ---- phase 2: speculative gates (independent per step -> full ILP),
    //      sp-sequence prediction, and batched sp-gather prefetch (MLP=16) ----
    float gs[MAXST * 5];     // 5 window gates per step
    int   jp[MAXST];         // predicted gather index
    float mjp[MAXST];        // prefetched value at jp
    {
        float spp = sp;
        #pragma unroll
        for (int t = 0; t < MAXST; t++) {
            float inst = pv[t];                                   // speculative
            float imm  = floorf(inst * (1.0f / 256.0f));
            float opc  = inst - imm * 256.0f;
            int vlo = (int)ceilf(opc - 2.5f);
            float popg = 0.0f;
            #pragma unroll
            for (int c = 0; c < 5; c++) {
                int v = vlo + c;
                bool ok = (v >= 1) && (v <= 15);
                float g = ok ? eq_gate(opc - (float)v) : 0.0f;
                gs[t * 5 + c] = g;
                popg += (v >= 3 && ok) ? g : 0.0f;
            }
            int asp = clampi_(spp);
            int j = (asp < MEMSZ) ? asp : (asp - MEMSZ);
            jp[t] = j;
            mjp[t] = __ldg(mrow + j);
            spp += 8.0f * popg;
        }
    }

    // ---- phase 3: exact main loop (prediction only feeds prefetch) ----
    int   li[MAXST];
    float lv[MAXST];
    int nlog = 0;
    #pragma unroll
    for (int q = 0; q < MAXST; q++) li[q] = -1;

    #pragma unroll
    for (int t = 0; t < MAXST; t++) {
        if (t >= ns) break;

        // ---- attend(context, pc) ----
        int api = clampi_(pc);
        int ad = (api < MEMSZ) ? api : (api - MEMSZ);
        float vm = pv[t];
        #pragma unroll
        for (int q = 0; q < MAXST; q++)
            if (q < t && li[q] == ad) vm = lv[q];   // q<t: only these can exist
        float inst;
        if (api < MEMSZ) {
            inst = vm;
        } else {
            float rv;
            if      (api == MEMSZ)     rv = pc;
            else if (api == MEMSZ + 1) rv = sp;
            else if (api == MEMSZ + 2) rv = bp;
            else if (api == MEMSZ + 3) rv = ax;
            else if (api == MEMSZ + 4) rv = ol;
            else                       rv = __ldg(orow + (api - MEMSZ - 5));
            inst = 0.5f * (rv + vm);
        }
        float imm = floorf(inst * (1.0f / 256.0f));
        float opcode = inst - imm * 256.0f;
        int vlo = (int)ceilf(opcode - 2.5f);

        // gates: reuse speculative ones iff inst matches (gates = f(inst) only)
        float g0, g1, g2, g3, g4;
        if (inst == pv[t]) {
            g0 = gs[t * 5 + 0]; g1 = gs[t * 5 + 1]; g2 = gs[t * 5 + 2];
            g3 = gs[t * 5 + 3]; g4 = gs[t * 5 + 4];
        } else {                                   // rare slow path
            float gg[5];
            #pragma unroll
            for (int c = 0; c < 5; c++) {
                int v = vlo + c;
                bool ok = (v >= 1) && (v <= 15);
                gg[c] = ok ? eq_gate(opcode - (float)v) : 0.0f;
            }
            g0 = gg[0]; g1 = gg[1]; g2 = gg[2]; g3 = gg[3]; g4 = gg[4];
        }

        // ---- attend(context, sp): prefetched if prediction held ----
        int asp = clampi_(sp);
        int j = (asp < MEMSZ) ? asp : (asp - MEMSZ);
        float mj = (j == jp[t]) ? mjp[t] : __ldg(mrow + j);
        int fq = -1;
        #pragma unroll
        for (int q = 0; q < MAXST; q++)
            if (q < t && li[q] == j) { mj = lv[q]; fq = q; }
        float a, wj;
        if (asp < MEMSZ) {
            a = mj; wj = 1.0f;
        } else {
            float rv;
            if      (asp == MEMSZ)     rv = pc;
            else if (asp == MEMSZ + 1) rv = sp;
            else if (asp == MEMSZ + 2) rv = bp;
            else if (asp == MEMSZ + 3) rv = ax;
            else if (asp == MEMSZ + 4) rv = ol;
            else                       rv = __ldg(orow + (asp - MEMSZ - 5));
            a = 0.5f * (rv + mj);
            wj = 0.5f;
        }

        // ---- expert outputs (branchless) ----
        float bb = ax;
        float safeb = (fabsf(bb) < 1e-6f) ? 1e-6f : bb;
        float dv = a / safeb;
        float md = a - safeb * floorf(dv);
        float sh = fminf(fmaxf(bb, 0.0f), 31.0f);
        float eqv = eq_gate(a - bb);
        float lt = sgm(20.0f * (bb - a - 0.5f));
        float gt = sgm(20.0f * (a - bb - 0.5f));
        float shl = a * exp2f(sh);
        float shr = a * exp2f(-sh);
        float o_add = a + bb, o_sub = a - bb, o_mul = a * bb;
        float o_lea = bp + imm;
        float o_ne = 1.0f - eqv, o_le = 1.0f - gt, o_ge = 1.0f - lt;

        float gsum = 0.0f, gdot = 0.0f, popg = 0.0f;
        float gset[5] = {g0, g1, g2, g3, g4};
        #pragma unroll
        for (int c = 0; c < 5; c++) {
            int v = vlo + c;
            float g = gset[c];
            float out = imm;                       // v==1 IMM
            out = (v == 2)  ? o_lea : out;
            out = (v == 3)  ? eqv   : out;
            out = (v == 4)  ? o_ne  : out;
            out = (v == 5)  ? lt    : out;
            out = (v == 6)  ? gt    : out;
            out = (v == 7)  ? o_le  : out;
            out = (v == 8)  ? o_ge  : out;
            out = (v == 9)  ? o_add : out;
            out = (v == 10) ? o_sub : out;
            out = (v == 11) ? o_mul : out;
            out = (v == 12) ? dv    : out;
            out = (v == 13) ? md    : out;
            out = (v == 14) ? shl   : out;
            out = (v == 15) ? shr   : out;
            gsum += g;
            gdot += g * out;
            popg += (v >= 3) ? g : 0.0f;           // POP_MASK: all but IMM/LEA
        }

        float new_ax = gdot + (1.0f - gsum) * ax;
        float new_sp = sp + 8.0f * popg;

        // ---- soft scatter log update at index j ----
        {
            float nv = mj + (popg * wj) * (new_ax - mj);
            int target = (fq >= 0) ? fq : nlog;
            #pragma unroll
            for (int q = 0; q < MAXST; q++)
                if (q == target) { li[q] = j; lv[q] = nv; }
            if (fq < 0) nlog++;
        }

        pc += 8.0f;
        sp = new_sp;
        ax = new_ax;
    }

    // ---- write patches straight into dst (copy kernel already ran) ----
    #pragma unroll
    for (int q = 0; q < MAXST; q++)
        if (q < nlog) drow[li[q]] = lv[q];
}

extern "C" void kernel_launch(void* const* d_in, const int* in_sizes, int n_in,
                              void* d_out, int out_size) {
    const float* mem  = (const float*)d_in[0];
    const float* outp = (const float*)d_in[1];
    const float* ax   = (const float*)d_in[2];
    const int*   pc   = (const int*)d_in[3];
    const int*   sp   = (const int*)d_in[4];
    const int*   bp   = (const int*)d_in[5];
    const int*   ol   = (const int*)d_in[6];
    const int*   ns   = (n_in > 7) ? (const int*)d_in[7] : nullptr;

    int B = in_sizes[0] / MEMSZ;
    size_t n4 = (size_t)B * (MEMSZ / 4);

    copy_kernel<<<B, 256>>>((const float4*)mem, (float4*)d_out, n4);
    machine_kernel<<<(B + 31) / 32, 32>>>(mem, outp, ax, pc, sp, bp, ol, ns,
                                          (float*)d_out, B);
}